// round 1
// baseline (speedup 1.0000x reference)
#include <cuda_runtime.h>
#include <math.h>

// Problem constants
constexpr int Bc   = 16;     // batch
constexpr int Cc   = 256;    // channels (DIM)
constexpr int Hh   = 128;
constexpr int Ww   = 128;
constexpr int NH   = 8;      // heads
constexpr int HD   = 32;     // head dim
constexpr int T    = 64;     // tokens per window (8x8)
constexpr int WIN  = 8;
constexpr int Hn   = Hh / WIN;   // 16
constexpr int Wn   = Ww / WIN;   // 16
constexpr float SCALE = 0.17677669529663687f;  // 32^-0.5

constexpr int TPB = 256;

// Shared memory layout (floats)
constexpr int SZ_TOK = 64 * 257;          // tokens [t][c], pad 257
constexpr int SZ_W   = 8448;              // weight chunk / staging buffer
constexpr int SZ_QKV = 64 * 33;           // per-head q/k/v, pad 33
constexpr int SZ_S   = 64 * 65;           // attn matrix, pad 65
constexpr int SZ_OUT = 64 * 257;          // attention output [t][c]

constexpr int OFF_TOK = 0;
constexpr int OFF_W   = OFF_TOK + SZ_TOK;
constexpr int OFF_Q   = OFF_W   + SZ_W;
constexpr int OFF_K   = OFF_Q   + SZ_QKV;
constexpr int OFF_V   = OFF_K   + SZ_QKV;
constexpr int OFF_S   = OFF_V   + SZ_QKV;
constexpr int OFF_O   = OFF_S   + SZ_S;
constexpr int OFF_BQ  = OFF_O   + SZ_OUT;   // 768 floats
constexpr int OFF_BP  = OFF_BQ  + 768;      // 256 floats
constexpr int SMEM_FLOATS = OFF_BP + 256;
constexpr int SMEM_BYTES  = SMEM_FLOATS * 4;  // ~211 KB

__global__ __launch_bounds__(TPB)
void win_attn_kernel(const float* __restrict__ x,
                     const float* __restrict__ w_qkv,
                     const float* __restrict__ b_qkv,
                     const float* __restrict__ w_proj,
                     const float* __restrict__ b_proj,
                     float* __restrict__ out)
{
    extern __shared__ float sm[];
    float* sTok = sm + OFF_TOK;
    float* sW   = sm + OFF_W;
    float* sQ   = sm + OFF_Q;
    float* sK   = sm + OFF_K;
    float* sV   = sm + OFF_V;
    float* sS   = sm + OFF_S;
    float* sOut = sm + OFF_O;
    float* sBq  = sm + OFF_BQ;
    float* sBp  = sm + OFF_BP;

    const int tid  = threadIdx.x;
    const int wIdx = blockIdx.x;               // 0..4095
    const int b    = wIdx >> 8;                // / (Hn*Wn)=256
    const int rem  = wIdx & 255;
    const int hn   = rem >> 4;
    const int wn   = rem & 15;

    const int hi0 = hn * WIN;
    const int wj0 = wn * WIN;

    // ---- Phase 1: gather window tokens into smem [t][c], load biases ----
    for (int l = tid; l < Cc * T; l += TPB) {
        int c  = l >> 6;        // /64
        int ij = l & 63;        // t = i*8 + j
        int i  = ij >> 3;
        int j  = ij & 7;
        float v = x[ ((size_t)(b * Cc + c) * Hh + (hi0 + i)) * Ww + (wj0 + j) ];
        sTok[ij * 257 + c] = v;
    }
    for (int l = tid; l < 768; l += TPB) sBq[l] = b_qkv[l];
    if (tid < 256) sBp[tid] = b_proj[tid];

    const int ty = tid >> 4;   // 0..15
    const int tx = tid & 15;   // 0..15

    // ---- Phase 2+3: per-head QKV GEMM + attention ----
    for (int h = 0; h < NH; h++) {
        // QKV head GEMM: (64 x 256) @ (256 x 96)  (cols: q[0:32] k[32:64] v[64:96])
        float acc[4][6];
        #pragma unroll
        for (int i = 0; i < 4; i++)
            #pragma unroll
            for (int j = 0; j < 6; j++) acc[i][j] = 0.f;

        const int r0 = ty * 4;   // token rows
        const int c0 = tx * 6;   // output cols within head-qkv block

        for (int kk = 0; kk < Cc; kk += 64) {
            __syncthreads();   // protect sW reuse / phase-1 completion
            // stage 96 x 64 weight chunk: rows = q/k/v rows of this head
            for (int l = tid; l < 96 * 64; l += TPB) {
                int row = l >> 6;
                int kc  = l & 63;
                int gr;
                if (row < 32)      gr = h * 32 + row;
                else if (row < 64) gr = 256 + h * 32 + (row - 32);
                else               gr = 512 + h * 32 + (row - 64);
                sW[row * 65 + kc] = w_qkv[gr * Cc + kk + kc];
            }
            __syncthreads();
            #pragma unroll 4
            for (int k = 0; k < 64; k++) {
                float a[4], bb[6];
                #pragma unroll
                for (int i = 0; i < 4; i++) a[i] = sTok[(r0 + i) * 257 + kk + k];
                #pragma unroll
                for (int j = 0; j < 6; j++) bb[j] = sW[(c0 + j) * 65 + k];
                #pragma unroll
                for (int i = 0; i < 4; i++)
                    #pragma unroll
                    for (int j = 0; j < 6; j++)
                        acc[i][j] = fmaf(a[i], bb[j], acc[i][j]);
            }
        }
        // write q/k/v with bias
        #pragma unroll
        for (int j = 0; j < 6; j++) {
            int col = c0 + j;
            float bias;
            float* dst;
            int d;
            if (col < 32)       { bias = sBq[h * 32 + col];            dst = sQ; d = col; }
            else if (col < 64)  { bias = sBq[256 + h * 32 + col - 32]; dst = sK; d = col - 32; }
            else                { bias = sBq[512 + h * 32 + col - 64]; dst = sV; d = col - 64; }
            #pragma unroll
            for (int i = 0; i < 4; i++)
                dst[(r0 + i) * 33 + d] = acc[i][j] + bias;
        }
        __syncthreads();

        // ---- S = Q K^T * scale  (64x64) ----
        {
            int r  = tid >> 2;         // 0..63
            int cb = tid & 3;          // 0..3 (16 cols each)
            float qreg[32];
            #pragma unroll
            for (int d = 0; d < 32; d++) qreg[d] = sQ[r * 33 + d];
            #pragma unroll
            for (int c = 0; c < 16; c++) {
                int col = cb * 16 + c;
                float dot = 0.f;
                #pragma unroll
                for (int d = 0; d < 32; d++)
                    dot = fmaf(qreg[d], sK[col * 33 + d], dot);
                sS[r * 65 + col] = dot * SCALE;
            }
        }
        __syncthreads();

        // ---- row softmax ----
        if (tid < 64) {
            float m = -1e30f;
            #pragma unroll 8
            for (int c = 0; c < 64; c++) m = fmaxf(m, sS[tid * 65 + c]);
            float s = 0.f;
            #pragma unroll 8
            for (int c = 0; c < 64; c++) {
                float e = __expf(sS[tid * 65 + c] - m);
                sS[tid * 65 + c] = e;
                s += e;
            }
            float inv = 1.f / s;
            #pragma unroll 8
            for (int c = 0; c < 64; c++) sS[tid * 65 + c] *= inv;
        }
        __syncthreads();

        // ---- O_h = P @ V  (64x32), write into sOut columns of this head ----
        {
            int r  = tid >> 2;
            int d0 = (tid & 3) * 8;
            float accv[8];
            #pragma unroll
            for (int j = 0; j < 8; j++) accv[j] = 0.f;
            #pragma unroll 4
            for (int kt = 0; kt < 64; kt++) {
                float p = sS[r * 65 + kt];
                #pragma unroll
                for (int j = 0; j < 8; j++)
                    accv[j] = fmaf(p, sV[kt * 33 + d0 + j], accv[j]);
            }
            #pragma unroll
            for (int j = 0; j < 8; j++)
                sOut[r * 257 + h * 32 + d0 + j] = accv[j];
        }
        __syncthreads();
    }

    // ---- Phase 4: projection (64 x 256) @ (256 x 256) + scatter ----
    for (int cb2 = 0; cb2 < 2; cb2++) {
        float acc[4][8];
        #pragma unroll
        for (int i = 0; i < 4; i++)
            #pragma unroll
            for (int j = 0; j < 8; j++) acc[i][j] = 0.f;

        const int r0 = ty * 4;
        const int c0 = tx * 8;     // col within 128-block

        for (int kk = 0; kk < Cc; kk += 64) {
            __syncthreads();
            for (int l = tid; l < 128 * 64; l += TPB) {
                int row = l >> 6;
                int kc  = l & 63;
                sW[row * 65 + kc] = w_proj[(cb2 * 128 + row) * Cc + kk + kc];
            }
            __syncthreads();
            #pragma unroll 4
            for (int k = 0; k < 64; k++) {
                float a[4], bb[8];
                #pragma unroll
                for (int i = 0; i < 4; i++) a[i] = sOut[(r0 + i) * 257 + kk + k];
                #pragma unroll
                for (int j = 0; j < 8; j++) bb[j] = sW[(c0 + j) * 65 + k];
                #pragma unroll
                for (int i = 0; i < 4; i++)
                    #pragma unroll
                    for (int j = 0; j < 8; j++)
                        acc[i][j] = fmaf(a[i], bb[j], acc[i][j]);
            }
        }
        __syncthreads();
        // stage result [t][c_local] into sW region (64 x 131 layout) with bias
        #pragma unroll
        for (int i = 0; i < 4; i++)
            #pragma unroll
            for (int j = 0; j < 8; j++)
                sW[(r0 + i) * 131 + c0 + j] = acc[i][j] + sBp[cb2 * 128 + c0 + j];
        __syncthreads();
        // coalesced scatter to (B,C,H,W)
        for (int l = tid; l < 128 * 64; l += TPB) {
            int cl = l >> 6;
            int ij = l & 63;
            int i  = ij >> 3;
            int j  = ij & 7;
            int c  = cb2 * 128 + cl;
            out[ ((size_t)(b * Cc + c) * Hh + (hi0 + i)) * Ww + (wj0 + j) ] = sW[ij * 131 + cl];
        }
        __syncthreads();
    }
}

extern "C" void kernel_launch(void* const* d_in, const int* in_sizes, int n_in,
                              void* d_out, int out_size)
{
    const float* x      = (const float*)d_in[0];
    const float* w_qkv  = (const float*)d_in[1];
    const float* b_qkv  = (const float*)d_in[2];
    const float* w_proj = (const float*)d_in[3];
    const float* b_proj = (const float*)d_in[4];
    float* out = (float*)d_out;

    static bool attr_set = false;
    if (!attr_set) {
        cudaFuncSetAttribute(win_attn_kernel,
                             cudaFuncAttributeMaxDynamicSharedMemorySize,
                             SMEM_BYTES);
        attr_set = true;
    }

    dim3 grid(Bc * Hn * Wn);   // 4096 windows
    dim3 block(TPB);
    win_attn_kernel<<<grid, block, SMEM_BYTES>>>(x, w_qkv, b_qkv, w_proj, b_proj, out);
}

// round 3
// speedup vs baseline: 1.7793x; 1.7793x over previous
#include <cuda_runtime.h>

// ---------------- constants ----------------
constexpr int TPB = 256;
constexpr float SCALE = 0.17677669529663687f;   // 32^-0.5

// shared-memory row strides (floats) — all even (LDS.64 alignment), odd/2-mod-32 for banks
constexpr int ST = 258;   // sTok / sOut row stride (64 rows x 256 cols)
constexpr int SWS = 34;   // sW staging stride (row = output column, 32 k's)
constexpr int SKS = 66;   // sK / sV / sS row stride

constexpr int OFF_TOK = 0;
constexpr int OFF_OUT = OFF_TOK + 64 * ST;
constexpr int OFF_W   = OFF_OUT + 64 * ST;
constexpr int OFF_K   = OFF_W   + 256 * SWS;
constexpr int OFF_V   = OFF_K   + 64 * SKS;
constexpr int OFF_S   = OFF_V   + 64 * SKS;
constexpr int OFF_BQ  = OFF_S   + 64 * SKS;
constexpr int OFF_BP  = OFF_BQ  + 768;
constexpr int SMEM_FLOATS = OFF_BP + 256;
constexpr int SMEM_BYTES  = SMEM_FLOATS * 4;   // ~216.5 KB

// ---------------- f32x2 helpers ----------------
__device__ __forceinline__ void ffma2(unsigned long long& d,
                                      unsigned long long a,
                                      unsigned long long b) {
    asm("fma.rn.f32x2 %0, %1, %2, %0;" : "+l"(d) : "l"(a), "l"(b));
}
__device__ __forceinline__ float fsum2(unsigned long long v) {
    float x, y;
    asm("mov.b64 {%0,%1}, %2;" : "=f"(x), "=f"(y) : "l"(v));
    return x + y;
}
__device__ __forceinline__ unsigned long long ld2s(const float* p) {
    return *reinterpret_cast<const unsigned long long*>(p);
}
__device__ __forceinline__ unsigned long long pk2(float lo, float hi) {
    unsigned long long r;
    asm("mov.b64 %0, {%1,%2};" : "=l"(r) : "f"(lo), "f"(hi));
    return r;
}

__global__ __launch_bounds__(TPB, 1)
void win_attn2(const float* __restrict__ x,
               const float* __restrict__ w_qkv,
               const float* __restrict__ b_qkv,
               const float* __restrict__ w_proj,
               const float* __restrict__ b_proj,
               float* __restrict__ out)
{
    extern __shared__ float sm[];
    float* sTok = sm + OFF_TOK;
    float* sOut = sm + OFF_OUT;   // Q per head then O per head (in place), A-operand of proj
    float* sW   = sm + OFF_W;     // weight staging: [out-col][k-chunk of 32]
    float* sKb  = sm + OFF_K;     // K for 2 heads: [token][64]
    float* sVb  = sm + OFF_V;     // V for 2 heads
    float* sS   = sm + OFF_S;     // attn matrix (one head)
    float* sBq  = sm + OFF_BQ;
    float* sBp  = sm + OFF_BP;

    const int tid  = threadIdx.x;
    const int wIdx = blockIdx.x;           // 0..4095
    const int b    = wIdx >> 8;
    const int hn   = (wIdx >> 4) & 15;
    const int wn   = wIdx & 15;
    const int hi0  = hn * 8, wj0 = wn * 8;

    // ---- Phase 1: gather window tokens (vectorized LDG.128, sector-exact) ----
    {
        #pragma unroll
        for (int it = 0; it < 16; it++) {
            int idx = it * 256 + tid;          // 4096 float4 tiles
            int jj = idx & 1;
            int i  = (idx >> 1) & 7;
            int c  = idx >> 4;
            const float4 v = *reinterpret_cast<const float4*>(
                x + (((size_t)(b * 256 + c) * 128 + hi0 + i) * 128 + wj0 + jj * 4));
            float* d = sTok + (i * 8 + jj * 4) * ST + c;
            d[0]      = v.x;
            d[ST]     = v.y;
            d[2 * ST] = v.z;
            d[3 * ST] = v.w;
        }
        for (int l = tid; l < 768; l += TPB) sBq[l] = b_qkv[l];
        if (tid < 256) sBp[tid] = b_proj[tid];
    }
    __syncthreads();

    const int ty = tid >> 5;   // warp id 0..7 -> 8 token rows each
    const int tx = tid & 31;
    const int r0 = ty * 8;

    // ---- Phase 2: QKV (2 heads per pass) + attention ----
    for (int pair = 0; pair < 4; pair++) {
        const int h0 = pair * 2;

        // 64x192 GEMM: rows = tokens, cols = [Q(h0),Q(h0+1) | K pair | V pair]
        unsigned long long acc[8][6];
        #pragma unroll
        for (int i = 0; i < 8; i++)
            #pragma unroll
            for (int j = 0; j < 6; j++) acc[i][j] = 0ull;

        for (int kc = 0; kc < 8; kc++) {
            const int kk = kc * 32;
            __syncthreads();                 // protect sW / sK / sV reuse
            // stage 192 rows x 32 k  (coalesced LDG, conflict-free STS)
            #pragma unroll
            for (int it = 0; it < 24; it++) {
                int row = it * 8 + ty;       // local out-col 0..191
                int sec = row >> 6;          // 0=q 1=k 2=v
                int w   = row & 63;
                sW[row * SWS + tx] = w_qkv[(sec * 256 + h0 * 32 + w) * 256 + kk + tx];
            }
            __syncthreads();

            const float* aB = sTok + r0 * ST + kk;
            const float* bB = sW + tx * SWS;
            #pragma unroll 4
            for (int k2 = 0; k2 < 32; k2 += 2) {
                unsigned long long a2[8], b2[6];
                #pragma unroll
                for (int i = 0; i < 8; i++) a2[i] = ld2s(aB + i * ST + k2);
                #pragma unroll
                for (int j = 0; j < 6; j++) b2[j] = ld2s(bB + j * 32 * SWS + k2);
                #pragma unroll
                for (int i = 0; i < 8; i++)
                    #pragma unroll
                    for (int j = 0; j < 6; j++) ffma2(acc[i][j], a2[i], b2[j]);
            }
        }

        // epilogue: add bias, route to Q(in sOut)/K/V
        #pragma unroll
        for (int j = 0; j < 6; j++) {
            const int sec = j >> 1;                 // c>>6 (tx<32)
            const int w   = tx + 32 * (j & 1);      // c&63
            const float bias = sBq[sec * 256 + h0 * 32 + w];
            float* dst;
            int stride;
            if (sec == 0)      { dst = sOut + h0 * 32 + w; stride = ST; }
            else if (sec == 1) { dst = sKb + w;            stride = SKS; }
            else               { dst = sVb + w;            stride = SKS; }
            #pragma unroll
            for (int i = 0; i < 8; i++)
                dst[(r0 + i) * stride] = fsum2(acc[i][j]) + bias;
        }
        __syncthreads();

        // ---- attention for the two heads of this pair ----
        #pragma unroll
        for (int hh = 0; hh < 2; hh++) {
            const int h   = h0 + hh;
            const int hc0 = h * 32;
            const int ks0 = hh * 32;

            // S = Q K^T * scale  (64x64), 4x4 tile per thread
            {
                const int ry = tid >> 4, cx = tid & 15;
                const int rs = ry * 4;
                unsigned long long sacc[4][4];
                #pragma unroll
                for (int i = 0; i < 4; i++)
                    #pragma unroll
                    for (int j = 0; j < 4; j++) sacc[i][j] = 0ull;
                const float* qB = sOut + rs * ST + hc0;
                const float* kB = sKb + cx * SKS + ks0;
                #pragma unroll 4
                for (int d2 = 0; d2 < 32; d2 += 2) {
                    unsigned long long q2[4], k2r[4];
                    #pragma unroll
                    for (int i = 0; i < 4; i++) q2[i]  = ld2s(qB + i * ST + d2);
                    #pragma unroll
                    for (int j = 0; j < 4; j++) k2r[j] = ld2s(kB + j * 16 * SKS + d2);
                    #pragma unroll
                    for (int i = 0; i < 4; i++)
                        #pragma unroll
                        for (int j = 0; j < 4; j++) ffma2(sacc[i][j], q2[i], k2r[j]);
                }
                #pragma unroll
                for (int i = 0; i < 4; i++)
                    #pragma unroll
                    for (int j = 0; j < 4; j++)
                        sS[(rs + i) * SKS + cx + 16 * j] = fsum2(sacc[i][j]) * SCALE;
            }
            __syncthreads();

            // row softmax: 4 lanes per row, shfl reductions
            {
                const int row = tid >> 2, q = tid & 3;
                float* p = sS + row * SKS + q * 16;
                float m = p[0];
                #pragma unroll
                for (int c = 1; c < 16; c++) m = fmaxf(m, p[c]);
                m = fmaxf(m, __shfl_xor_sync(0xFFFFFFFF, m, 1));
                m = fmaxf(m, __shfl_xor_sync(0xFFFFFFFF, m, 2));
                float e[16];
                float s = 0.f;
                #pragma unroll
                for (int c = 0; c < 16; c++) { e[c] = __expf(p[c] - m); s += e[c]; }
                s += __shfl_xor_sync(0xFFFFFFFF, s, 1);
                s += __shfl_xor_sync(0xFFFFFFFF, s, 2);
                const float inv = 1.f / s;
                #pragma unroll
                for (int c = 0; c < 16; c++) p[c] = e[c] * inv;
            }
            __syncthreads();

            // O_h = P @ V  (64x32) -> in place into sOut head columns
            {
                const int ry = tid >> 4, cx = tid & 15;
                const int rs = ry * 4;
                unsigned long long oacc[4][2];
                #pragma unroll
                for (int i = 0; i < 4; i++) { oacc[i][0] = 0ull; oacc[i][1] = 0ull; }
                const float* pB = sS + rs * SKS;
                const float* vB = sVb + ks0 + cx;
                #pragma unroll 4
                for (int t2 = 0; t2 < 64; t2 += 2) {
                    unsigned long long p2[4];
                    #pragma unroll
                    for (int i = 0; i < 4; i++) p2[i] = ld2s(pB + i * SKS + t2);
                    unsigned long long v2[2];
                    #pragma unroll
                    for (int j = 0; j < 2; j++)
                        v2[j] = pk2(vB[t2 * SKS + 16 * j], vB[(t2 + 1) * SKS + 16 * j]);
                    #pragma unroll
                    for (int i = 0; i < 4; i++) {
                        ffma2(oacc[i][0], p2[i], v2[0]);
                        ffma2(oacc[i][1], p2[i], v2[1]);
                    }
                }
                #pragma unroll
                for (int i = 0; i < 4; i++)
                    #pragma unroll
                    for (int j = 0; j < 2; j++)
                        sOut[(rs + i) * ST + hc0 + cx + 16 * j] = fsum2(oacc[i][j]);
            }
            __syncthreads();
        }
    }

    // ---- Phase 3: projection 64x256 @ 256x256, 8x8 tile (col-paired f32x2) ----
    {
        unsigned long long pacc[8][4];   // pair p covers cols tx+64p, tx+64p+32
        #pragma unroll
        for (int i = 0; i < 8; i++)
            #pragma unroll
            for (int p = 0; p < 4; p++) pacc[i][p] = 0ull;

        for (int kc = 0; kc < 8; kc++) {
            const int kk = kc * 32;
            __syncthreads();
            #pragma unroll
            for (int it = 0; it < 32; it++) {
                int row = it * 8 + ty;   // output col 0..255
                sW[row * SWS + tx] = w_proj[row * 256 + kk + tx];
            }
            __syncthreads();

            const float* aB = sOut + r0 * ST + kk;
            const float* bB = sW + tx * SWS;
            #pragma unroll 2
            for (int k = 0; k < 32; k++) {
                float a[8], bv[8];
                #pragma unroll
                for (int i = 0; i < 8; i++) a[i]  = aB[i * ST + k];
                #pragma unroll
                for (int j = 0; j < 8; j++) bv[j] = bB[j * 32 * SWS + k];
                unsigned long long ad[8], bp[4];
                #pragma unroll
                for (int i = 0; i < 8; i++) ad[i] = pk2(a[i], a[i]);
                #pragma unroll
                for (int p = 0; p < 4; p++) bp[p] = pk2(bv[2 * p], bv[2 * p + 1]);
                #pragma unroll
                for (int i = 0; i < 8; i++)
                    #pragma unroll
                    for (int p = 0; p < 4; p++) ffma2(pacc[i][p], ad[i], bp[p]);
            }
        }

        // epilogue: bias + direct aligned STG.128 scatter (token rows are contiguous)
        #pragma unroll
        for (int p = 0; p < 4; p++) {
            #pragma unroll
            for (int half = 0; half < 2; half++) {
                const int c = tx + 64 * p + 32 * half;
                const float bias = sBp[c];
                float vals[8];
                #pragma unroll
                for (int i = 0; i < 8; i++) {
                    float xx, yy;
                    asm("mov.b64 {%0,%1}, %2;" : "=f"(xx), "=f"(yy) : "l"(pacc[i][p]));
                    vals[i] = (half == 0 ? xx : yy) + bias;
                }
                float* o = out + (((size_t)(b * 256 + c) * 128 + hi0 + ty) * 128 + wj0);
                *reinterpret_cast<float4*>(o)     = make_float4(vals[0], vals[1], vals[2], vals[3]);
                *reinterpret_cast<float4*>(o + 4) = make_float4(vals[4], vals[5], vals[6], vals[7]);
            }
        }
    }
}

extern "C" void kernel_launch(void* const* d_in, const int* in_sizes, int n_in,
                              void* d_out, int out_size)
{
    const float* x      = (const float*)d_in[0];
    const float* w_qkv  = (const float*)d_in[1];
    const float* b_qkv  = (const float*)d_in[2];
    const float* w_proj = (const float*)d_in[3];
    const float* b_proj = (const float*)d_in[4];
    float* out = (float*)d_out;

    static bool attr_set = false;
    if (!attr_set) {
        cudaFuncSetAttribute(win_attn2,
                             cudaFuncAttributeMaxDynamicSharedMemorySize,
                             SMEM_BYTES);
        attr_set = true;
    }

    win_attn2<<<4096, TPB, SMEM_BYTES>>>(x, w_qkv, b_qkv, w_proj, b_proj, out);
}